// round 1
// baseline (speedup 1.0000x reference)
#include <cuda_runtime.h>

// =============================================================================
// RAFF_8555574853896 — fused attention + per-position classifiers + heads
//
// Algebraic restructuring (exact in exact arithmetic; fp32 throughout):
//   scores = q M q^T / sqrt(D) + rank-1 bias terms,   M = Wq^T Wk
//   audio  = (w_a^T q) Cov^T + bcomb,                 Cov = out_w Wv
//   with w_a = d_a^T attn (and likewise video), valid because softmax rows
//   sum to 1 so the biases commute through the weighted sums.
// =============================================================================

namespace raff {

constexpr int B = 2048, S = 32, P = 16, D = 1024, H = 512, F = 512;

// ---- static device scratch (no allocations allowed) ----
__device__ float g_M[D * D];                 // Wq^T Wk
__device__ float g_Cov[D * D];               // out_w @ Wv
__device__ float g_vq[D];                    // bq @ Wk
__device__ float g_vk[D];                    // bk @ Wq
__device__ float g_bcomb[D];                 // out_w @ bv + out_b
__device__ float g_c0;                       // bq . bk
__device__ float g_qM[(long)B * S * D];      // q @ M (+vq)          256 MB
__device__ float g_h[(long)S * B * H];       // classifier hidden     128 MB
__device__ float g_d[B * S];                 // classifier logits
__device__ float g_qv[2L * B * D];           // weighted q sums (a,v)
__device__ float g_av[2L * B * D];           // audio, video
__device__ float g_fusion[(long)B * D];      // (audio+video)/2
__device__ float g_y[3L * B * F];            // pre-LN head outputs

// =============================================================================
// Generic fp32 tiled GEMM: C = op(A) * op(B) (+bias) (+relu)
//   TA=false: A is [M,K] row-major.  TA=true: A is [K,M] row-major (A^T view).
//   TB=false: B is [K,N] row-major.  TB=true: B is [N,K] row-major (B^T view).
// Tile 128x128x16, 256 threads, 8x8 per-thread microtile.
// All shapes used here are multiples of (128,128,16) -> no bounds checks.
// Batched via blockIdx.z with byte-free (element) strides.
// =============================================================================
template <bool TA, bool TB, bool RELU, bool BIAS>
__global__ void __launch_bounds__(256) gemm128(
    const float* __restrict__ A, int lda, long sA,
    const float* __restrict__ Bm, int ldb, long sB,
    float* __restrict__ C, int ldc, long sC,
    const float* __restrict__ bias, long sBias,
    int M, int N, int K)
{
    constexpr int BM = 128, BN = 128, BK = 16;
    __shared__ float As[BK][BM];
    __shared__ float Bs[BK][BN];

    const int z = blockIdx.z;
    A += (long)z * sA;
    Bm += (long)z * sB;
    C += (long)z * sC;
    if (BIAS) bias += (long)z * sBias;

    const int m0 = blockIdx.y * BM;
    const int n0 = blockIdx.x * BN;
    const int tid = threadIdx.x;
    const int tx = tid & 15;   // 0..15 -> n
    const int ty = tid >> 4;   // 0..15 -> m

    float acc[8][8];
#pragma unroll
    for (int i = 0; i < 8; i++)
#pragma unroll
        for (int j = 0; j < 8; j++) acc[i][j] = 0.0f;

    for (int k0 = 0; k0 < K; k0 += BK) {
        // ---- load A tile into As[k][m] ----
        if (!TA) {
            const int r = tid >> 2;            // 0..63 (m)
            const int c4 = (tid & 3) * 4;      // 0,4,8,12 (k)
#pragma unroll
            for (int i = 0; i < 2; i++) {
                const int m = r + i * 64;
                float4 v = *(const float4*)&A[(long)(m0 + m) * lda + k0 + c4];
                As[c4 + 0][m] = v.x; As[c4 + 1][m] = v.y;
                As[c4 + 2][m] = v.z; As[c4 + 3][m] = v.w;
            }
        } else {
            const int r = tid >> 5;            // 0..7 (k)
            const int c4 = (tid & 31) * 4;     // 0..124 (m)
#pragma unroll
            for (int i = 0; i < 2; i++) {
                const int k = r + i * 8;
                *(float4*)&As[k][c4] =
                    *(const float4*)&A[(long)(k0 + k) * lda + m0 + c4];
            }
        }
        // ---- load B tile into Bs[k][n] ----
        if (!TB) {
            const int r = tid >> 5;            // 0..7 (k)
            const int c4 = (tid & 31) * 4;     // 0..124 (n)
#pragma unroll
            for (int i = 0; i < 2; i++) {
                const int k = r + i * 8;
                *(float4*)&Bs[k][c4] =
                    *(const float4*)&Bm[(long)(k0 + k) * ldb + n0 + c4];
            }
        } else {
            const int r = tid >> 2;            // 0..63 (n)
            const int c4 = (tid & 3) * 4;      // 0,4,8,12 (k)
#pragma unroll
            for (int i = 0; i < 2; i++) {
                const int n = r + i * 64;
                float4 v = *(const float4*)&Bm[(long)(n0 + n) * ldb + k0 + c4];
                Bs[c4 + 0][n] = v.x; Bs[c4 + 1][n] = v.y;
                Bs[c4 + 2][n] = v.z; Bs[c4 + 3][n] = v.w;
            }
        }
        __syncthreads();

#pragma unroll
        for (int k = 0; k < BK; k++) {
            float a[8], b[8];
            *(float4*)&a[0] = *(float4*)&As[k][ty * 8];
            *(float4*)&a[4] = *(float4*)&As[k][ty * 8 + 4];
            *(float4*)&b[0] = *(float4*)&Bs[k][tx * 8];
            *(float4*)&b[4] = *(float4*)&Bs[k][tx * 8 + 4];
#pragma unroll
            for (int i = 0; i < 8; i++)
#pragma unroll
                for (int j = 0; j < 8; j++)
                    acc[i][j] = fmaf(a[i], b[j], acc[i][j]);
        }
        __syncthreads();
    }

    // ---- epilogue ----
#pragma unroll
    for (int i = 0; i < 8; i++) {
        const int m = m0 + ty * 8 + i;
#pragma unroll
        for (int j = 0; j < 8; j += 4) {
            const int n = n0 + tx * 8 + j;
            float4 v = make_float4(acc[i][j], acc[i][j + 1], acc[i][j + 2], acc[i][j + 3]);
            if (BIAS) {
                v.x += bias[n]; v.y += bias[n + 1];
                v.z += bias[n + 2]; v.w += bias[n + 3];
            }
            if (RELU) {
                v.x = fmaxf(v.x, 0.f); v.y = fmaxf(v.y, 0.f);
                v.z = fmaxf(v.z, 0.f); v.w = fmaxf(v.w, 0.f);
            }
            *(float4*)&C[(long)m * ldc + n] = v;
        }
    }
}

// =============================================================================
// Small vector precomputations: vq, vk, bcomb, c0 (all bias-derived).
// =============================================================================
__global__ void vec_pre(const float* __restrict__ in_proj_w,
                        const float* __restrict__ in_proj_b,
                        const float* __restrict__ out_w,
                        const float* __restrict__ out_b)
{
    const int i = blockIdx.x * 256 + threadIdx.x;  // 0..1023
    const float* wq = in_proj_w;
    const float* wk = in_proj_w + (long)D * D;
    const float* bq = in_proj_b;
    const float* bk = in_proj_b + D;
    const float* bv = in_proj_b + 2 * D;
    float vq = 0.f, vk = 0.f, bc = 0.f;
    for (int e = 0; e < D; e++) {
        vq = fmaf(bq[e], wk[(long)e * D + i], vq);
        vk = fmaf(bk[e], wq[(long)e * D + i], vk);
        bc = fmaf(out_w[(long)i * D + e], bv[e], bc);
    }
    g_vq[i] = vq;
    g_vk[i] = vk;
    g_bcomb[i] = bc + out_b[i];
    if (i == 0) {
        float c = 0.f;
        for (int e = 0; e < D; e++) c = fmaf(bq[e], bk[e], c);
        g_c0 = c;
    }
}

// =============================================================================
// Classifier reduction: d[b,s] = relu(h[s,b,:] . w2[s] + b2[s]). One warp/row.
// =============================================================================
__global__ void cls_reduce(const float* __restrict__ cls_w2,
                           const float* __restrict__ cls_b2)
{
    const int warp = (blockIdx.x * blockDim.x + threadIdx.x) >> 5;
    const int lane = threadIdx.x & 31;
    const int s = warp >> 11;      // warp / 2048
    const int b = warp & 2047;
    const float* hrow = g_h + ((long)s * B + b) * H;
    const float* w = cls_w2 + (long)s * H;
    float acc = 0.f;
#pragma unroll
    for (int i = 0; i < H / 128; i++) {
        float4 hv = *(const float4*)&hrow[(lane + 32 * i) * 4];
        float4 wv = *(const float4*)&w[(lane + 32 * i) * 4];
        acc = fmaf(hv.x, wv.x, acc);
        acc = fmaf(hv.y, wv.y, acc);
        acc = fmaf(hv.z, wv.z, acc);
        acc = fmaf(hv.w, wv.w, acc);
    }
#pragma unroll
    for (int o = 16; o > 0; o >>= 1) acc += __shfl_xor_sync(~0u, acc, o);
    if (lane == 0) g_d[b * S + s] = fmaxf(acc + cls_b2[s], 0.f);
}

// =============================================================================
// Per-batch attention: scores (32x32 via qM . q^T), softmax, d_a/d_v softmax,
// w_a/w_v = d^T attn, qv = w^T q. One block per batch element.
// =============================================================================
__global__ void __launch_bounds__(256) attn_kernel(
    const float* __restrict__ q, float* __restrict__ out)
{
    const int b = blockIdx.x;
    __shared__ float qs[32][132];
    __shared__ float qms[32][132];
    __shared__ float sc[32][33];
    __shared__ float vks[128];
    __shared__ float dd[32], rk[32], wa[32], wvv[32], da[16], dv[16];

    const int tid = threadIdx.x;
    const int s = tid >> 3;
    const int tb = tid & 7;
    const float* qb = q + (long)b * S * D;
    const float* qmb = g_qM + (long)b * S * D;

    if (tid < 32) dd[tid] = g_d[b * S + tid];

    float racc[4] = {0.f, 0.f, 0.f, 0.f};
    float rkacc = 0.f;

    for (int c = 0; c < D; c += 128) {
#pragma unroll
        for (int i = 0; i < 4; i++) {
            const int f = tid + 256 * i;
            const int r = f >> 5;
            const int c4 = (f & 31) << 2;
            *(float4*)&qs[r][c4] = *(const float4*)&qb[(long)r * D + c + c4];
            *(float4*)&qms[r][c4] = *(const float4*)&qmb[(long)r * D + c + c4];
        }
        if (tid < 32) *(float4*)&vks[tid * 4] = *(const float4*)&g_vk[c + tid * 4];
        __syncthreads();

#pragma unroll 4
        for (int k = 0; k < 128; k++) {
            const float av = qms[s][k];
#pragma unroll
            for (int j = 0; j < 4; j++)
                racc[j] = fmaf(av, qs[tb + 8 * j][k], racc[j]);
        }
        if (tid < 32) {
            float r2 = 0.f;
#pragma unroll 4
            for (int k = 0; k < 128; k++) r2 = fmaf(qs[tid][k], vks[k], r2);
            rkacc += r2;
        }
        __syncthreads();
    }

#pragma unroll
    for (int j = 0; j < 4; j++) sc[s][tb + 8 * j] = racc[j];
    if (tid < 32) rk[tid] = rkacc;
    __syncthreads();

    // row softmax over t (one warp per 4 rows)
    const int w = tid >> 5, lane = tid & 31;
    const float inv_sqrtD = 0.03125f;  // 1/sqrt(1024)
    for (int rr = w * 4; rr < w * 4 + 4; rr++) {
        float v = (sc[rr][lane] + rk[rr] + g_c0) * inv_sqrtD;
        float mx = v;
#pragma unroll
        for (int o = 16; o > 0; o >>= 1) mx = fmaxf(mx, __shfl_xor_sync(~0u, mx, o));
        float e = __expf(v - mx);
        float sum = e;
#pragma unroll
        for (int o = 16; o > 0; o >>= 1) sum += __shfl_xor_sync(~0u, sum, o);
        sc[rr][lane] = e / sum;
    }
    __syncthreads();

    // d softmaxes: lanes 0-15 audio, 16-31 video (xor<=8 stays in half-warp)
    if (tid < 32) {
        const bool isA = tid < 16;
        const int i = tid & 15;
        float v = dd[tid];
        float mx = v;
#pragma unroll
        for (int o = 8; o > 0; o >>= 1) mx = fmaxf(mx, __shfl_xor_sync(~0u, mx, o));
        float e = __expf(v - mx);
        float sum = e;
#pragma unroll
        for (int o = 8; o > 0; o >>= 1) sum += __shfl_xor_sync(~0u, sum, o);
        const float p = e / sum;
        if (isA) da[i] = p; else dv[i] = p;
        const long base = 3L * B * F;
        if (isA) out[base + (long)b * P + i] = p;
        else     out[base + (long)B * P + (long)b * P + i] = p;
    }
    __syncthreads();

    if (tid < 32) {
        float a = 0.f, v2 = 0.f;
#pragma unroll
        for (int ss = 0; ss < 16; ss++) a = fmaf(da[ss], sc[ss][tid], a);
#pragma unroll
        for (int ss = 0; ss < 16; ss++) v2 = fmaf(dv[ss], sc[16 + ss][tid], v2);
        wa[tid] = a;
        wvv[tid] = v2;
    }
    __syncthreads();

#pragma unroll
    for (int i = 0; i < 4; i++) {
        const int col = tid + 256 * i;
        float a = 0.f, v2 = 0.f;
#pragma unroll
        for (int t = 0; t < 32; t++) {
            const float x = qb[(long)t * D + col];
            a = fmaf(wa[t], x, a);
            v2 = fmaf(wvv[t], x, v2);
        }
        g_qv[(long)b * D + col] = a;
        g_qv[(long)B * D + (long)b * D + col] = v2;
    }
}

// =============================================================================
// fusion = 0.5 * (audio + video)
// =============================================================================
__global__ void fuse_avg()
{
    const long i = (long)blockIdx.x * 256 + threadIdx.x;
    g_fusion[i] = 0.5f * (g_av[i] + g_av[(long)B * D + i]);
}

// =============================================================================
// LayerNorm(512) + ReLU per row, writing final outputs.
// =============================================================================
__global__ void __launch_bounds__(128) ln_relu(
    const float* __restrict__ gm0, const float* __restrict__ be0,
    const float* __restrict__ gm1, const float* __restrict__ be1,
    const float* __restrict__ gm2, const float* __restrict__ be2,
    float* __restrict__ out)
{
    const int head = blockIdx.y, b = blockIdx.x, tid = threadIdx.x;
    const float* gm = head == 0 ? gm0 : (head == 1 ? gm1 : gm2);
    const float* be = head == 0 ? be0 : (head == 1 ? be1 : be2);
    const float* y = g_y + ((long)head * B + b) * F;

    float4 v = *(const float4*)&y[tid * 4];
    float s = v.x + v.y + v.z + v.w;
    float sq = v.x * v.x + v.y * v.y + v.z * v.z + v.w * v.w;
#pragma unroll
    for (int o = 16; o > 0; o >>= 1) {
        s += __shfl_xor_sync(~0u, s, o);
        sq += __shfl_xor_sync(~0u, sq, o);
    }
    __shared__ float ss[4], ssq[4];
    const int w = tid >> 5;
    if ((tid & 31) == 0) { ss[w] = s; ssq[w] = sq; }
    __syncthreads();
    s = ss[0] + ss[1] + ss[2] + ss[3];
    sq = ssq[0] + ssq[1] + ssq[2] + ssq[3];
    const float mean = s * (1.f / F);
    const float var = sq * (1.f / F) - mean * mean;
    const float rstd = rsqrtf(var + 1e-5f);

    float4 g4 = *(const float4*)&gm[tid * 4];
    float4 b4 = *(const float4*)&be[tid * 4];
    float4 o4;
    o4.x = fmaxf((v.x - mean) * rstd * g4.x + b4.x, 0.f);
    o4.y = fmaxf((v.y - mean) * rstd * g4.y + b4.y, 0.f);
    o4.z = fmaxf((v.z - mean) * rstd * g4.z + b4.z, 0.f);
    o4.w = fmaxf((v.w - mean) * rstd * g4.w + b4.w, 0.f);
    *(float4*)&out[((long)head * B + b) * F + tid * 4] = o4;
}

}  // namespace raff

// =============================================================================
// Launch
// =============================================================================
extern "C" void kernel_launch(void* const* d_in, const int* in_sizes, int n_in,
                              void* d_out, int out_size)
{
    using namespace raff;
    (void)in_sizes; (void)n_in; (void)out_size;

    const float* q         = (const float*)d_in[0];
    const float* in_proj_w = (const float*)d_in[1];
    const float* in_proj_b = (const float*)d_in[2];
    const float* out_w     = (const float*)d_in[3];
    const float* out_b     = (const float*)d_in[4];
    const float* cls_w1    = (const float*)d_in[5];
    const float* cls_b1    = (const float*)d_in[6];
    const float* cls_w2    = (const float*)d_in[7];
    const float* cls_b2    = (const float*)d_in[8];
    const float* fus_w     = (const float*)d_in[9];
    const float* fus_b     = (const float*)d_in[10];
    const float* fus_g     = (const float*)d_in[11];
    const float* fus_be    = (const float*)d_in[12];
    const float* pa_w      = (const float*)d_in[13];
    const float* pa_b      = (const float*)d_in[14];
    const float* pa_g      = (const float*)d_in[15];
    const float* pa_be     = (const float*)d_in[16];
    const float* pv_w      = (const float*)d_in[17];
    const float* pv_b      = (const float*)d_in[18];
    const float* pv_g      = (const float*)d_in[19];
    const float* pv_be     = (const float*)d_in[20];
    float* out = (float*)d_out;

    float *pM, *pCov, *pqM, *ph, *pqv, *pav, *pfus, *py, *pvq, *pbcomb;
    cudaGetSymbolAddress((void**)&pM, g_M);
    cudaGetSymbolAddress((void**)&pCov, g_Cov);
    cudaGetSymbolAddress((void**)&pqM, g_qM);
    cudaGetSymbolAddress((void**)&ph, g_h);
    cudaGetSymbolAddress((void**)&pqv, g_qv);
    cudaGetSymbolAddress((void**)&pav, g_av);
    cudaGetSymbolAddress((void**)&pfus, g_fusion);
    cudaGetSymbolAddress((void**)&py, g_y);
    cudaGetSymbolAddress((void**)&pvq, g_vq);
    cudaGetSymbolAddress((void**)&pbcomb, g_bcomb);

    // 1) bias-derived vectors
    vec_pre<<<D / 256, 256>>>(in_proj_w, in_proj_b, out_w, out_b);

    // 2) M = Wq^T Wk   (TN)
    gemm128<true, false, false, false><<<dim3(8, 8), 256>>>(
        in_proj_w, D, 0L, in_proj_w + (long)D * D, D, 0L,
        pM, D, 0L, nullptr, 0L, D, D, D);

    // 3) Cov = out_w @ Wv   (NN)
    gemm128<false, false, false, false><<<dim3(8, 8), 256>>>(
        out_w, D, 0L, in_proj_w + 2L * D * D, D, 0L,
        pCov, D, 0L, nullptr, 0L, D, D, D);

    // 4) qM = q @ M + vq   (NN, the big one: 65536x1024x1024)
    gemm128<false, false, false, true><<<dim3(8, 512), 256>>>(
        q, D, 0L, pM, D, 0L, pqM, D, 0L, pvq, 0L, B * S, D, D);

    // 5) classifier hidden: h[s] = relu(q[:,s,:] @ w1[s]^T + b1[s])  (NT, batched z=32)
    gemm128<false, true, true, true><<<dim3(4, 16, 32), 256>>>(
        q, S * D, (long)D, cls_w1, D, (long)H * D,
        ph, H, (long)B * H, cls_b1, (long)H, B, H, D);

    // 6) d[b,s] = relu(h . w2 + b2)
    cls_reduce<<<(B * S) / 8, 256>>>(cls_w2, cls_b2);

    // 7) per-batch attention + classifier softmaxes + weighted sums
    attn_kernel<<<B, 256>>>(q, out);

    // 8) [audio; video] = qv @ Cov^T + bcomb   (NT, 4096x1024x1024)
    gemm128<false, true, false, true><<<dim3(8, 32), 256>>>(
        pqv, D, 0L, pCov, D, 0L, pav, D, 0L, pbcomb, 0L, 2 * B, D, D);

    // 9) fusion = 0.5 * (audio + video)
    fuse_avg<<<(B * D) / 256, 256>>>();

    // 10) three head GEMMs (NT, 2048x512x1024 each)
    gemm128<false, true, false, true><<<dim3(4, 16), 256>>>(
        pfus, D, 0L, fus_w, D, 0L, py, F, 0L, fus_b, 0L, B, F, D);
    gemm128<false, true, false, true><<<dim3(4, 16), 256>>>(
        pav, D, 0L, pa_w, D, 0L, py + (long)B * F, F, 0L, pa_b, 0L, B, F, D);
    gemm128<false, true, false, true><<<dim3(4, 16), 256>>>(
        pav + (long)B * D, D, 0L, pv_w, D, 0L, py + 2L * B * F, F, 0L, pv_b, 0L, B, F, D);

    // 11) LayerNorm + ReLU -> final outputs
    ln_relu<<<dim3(B, 3), 128>>>(fus_g, fus_be, pa_g, pa_be, pv_g, pv_be, out);
}

// round 3
// speedup vs baseline: 2.4456x; 2.4456x over previous
#include <cuda_runtime.h>
#include <cuda_bf16.h>
#include <cstdint>

// =============================================================================
// RAFF_8555574853896 — round 3: all GEMMs on warp-level HMMA (mma.sync bf16,
// hi/lo split, fp32 accum). tcgen05 is NOT available (harness PTX target is
// base sm_103); mma.sync/ldmatrix/cp.async are.
//
// Algebra (exact; validated round 1 at rel_err 1.3e-6):
//   scores = q Mt^T q^T / sqrt(D) + rank-1 bias,  Mt = (Wq^T Wk)^T
//   audio  = (w_a^T q) Cov^T + bcomb,             Cov = out_w Wv
// Split trick: x = hi + lo (bf16); A*B ~= Ahi*Bhi + Ahi*Blo + Alo*Bhi (~1e-5)
// =============================================================================

namespace raff {

constexpr int B = 2048, S = 32, P = 16, D = 1024, H = 512, F = 512;
constexpr long NQ = (long)B * S * D;

// ---------------- static device scratch ----------------
__device__ float g_vq[D], g_vk[D], g_bcomb[D];
__device__ float g_c0;
__device__ float g_Mt[D * D];
__device__ float g_Cov[D * D];
__device__ float g_qM[NQ];                     // 256 MB
__device__ float g_h[(long)S * B * H];         // 128 MB
__device__ float g_d[B * S];
__device__ float g_qv[2L * B * D];
__device__ float g_av[2L * B * D];
__device__ float g_fusion[(long)B * D];
__device__ float g_y[3L * B * F];

__device__ __nv_bfloat16 g_q_hi[NQ], g_q_lo[NQ];
__device__ __nv_bfloat16 g_w1_hi[(long)S * H * D], g_w1_lo[(long)S * H * D];
__device__ __nv_bfloat16 g_WqT_hi[D * D], g_WqT_lo[D * D];
__device__ __nv_bfloat16 g_WkT_hi[D * D], g_WkT_lo[D * D];
__device__ __nv_bfloat16 g_WvT_hi[D * D], g_WvT_lo[D * D];
__device__ __nv_bfloat16 g_ow_hi[D * D], g_ow_lo[D * D];
__device__ __nv_bfloat16 g_mt_hi[D * D], g_mt_lo[D * D];
__device__ __nv_bfloat16 g_cov_hi[D * D], g_cov_lo[D * D];
__device__ __nv_bfloat16 g_qv_hi[2L * B * D], g_qv_lo[2L * B * D];
__device__ __nv_bfloat16 g_x_hi[3L * B * D], g_x_lo[3L * B * D];
__device__ __nv_bfloat16 g_hw_hi[3L * F * D], g_hw_lo[3L * F * D];

// ---------------- PTX helpers (base sm_103-legal only) ----------------
__device__ __forceinline__ uint32_t smem_u32(const void* p) {
    uint32_t a;
    asm("{ .reg .u64 t; cvta.to.shared.u64 t, %1; cvt.u32.u64 %0, t; }"
        : "=r"(a) : "l"(p));
    return a;
}
#define CP16(dst, src) \
    asm volatile("cp.async.cg.shared.global [%0], [%1], 16;" :: "r"(dst), "l"(src))
#define CP_COMMIT() asm volatile("cp.async.commit_group;" ::: "memory")

__device__ __forceinline__ void ldsm_x4(uint32_t* r, uint32_t addr) {
    asm volatile("ldmatrix.sync.aligned.m8n8.x4.shared.b16 {%0,%1,%2,%3}, [%4];"
                 : "=r"(r[0]), "=r"(r[1]), "=r"(r[2]), "=r"(r[3]) : "r"(addr));
}
__device__ __forceinline__ void ldsm_x2(uint32_t* r, uint32_t addr) {
    asm volatile("ldmatrix.sync.aligned.m8n8.x2.shared.b16 {%0,%1}, [%2];"
                 : "=r"(r[0]), "=r"(r[1]) : "r"(addr));
}
__device__ __forceinline__ void mma_bf16(float* c, const uint32_t* a, const uint32_t* b) {
    asm volatile(
        "mma.sync.aligned.m16n8k16.row.col.f32.bf16.bf16.f32 "
        "{%0,%1,%2,%3}, {%4,%5,%6,%7}, {%8,%9}, {%0,%1,%2,%3};"
        : "+f"(c[0]), "+f"(c[1]), "+f"(c[2]), "+f"(c[3])
        : "r"(a[0]), "r"(a[1]), "r"(a[2]), "r"(a[3]), "r"(b[0]), "r"(b[1]));
}

// Swizzled tile address for (row, 16B-chunk): rows of 64B (32 bf16), 4 chunks.
// chunk XOR (row>>1)&3 -> conflict-free ldmatrix phases AND cp.async stores.
__device__ __forceinline__ uint32_t swz(int r, int c) {
    return (uint32_t)((r * 4 + (c ^ ((r >> 1) & 3))) * 16);
}

// =============================================================================
// HMMA split-bf16 GEMM: C[M,N] = A[M,K]*B[N,K]^T (+bias[n]) (+relu), fp32 out
// K = 1024. Block tile 128x128x32, 8 warps (2m x 4n), 2-stage cp.async.
// Grid: (N/128, M/128, Z).
// =============================================================================
constexpr int STAGE = 32768;                 // Ahi 8K | Alo 8K | Bhi 8K | Blo 8K
constexpr int GEMM_SMEM = 2 * STAGE;         // 64 KB

template <bool RELU, bool BIAS>
__global__ void __launch_bounds__(256) bsgemm(
    const __nv_bfloat16* __restrict__ Ahi, const __nv_bfloat16* __restrict__ Alo,
    long lda, long aOffZ,
    const __nv_bfloat16* __restrict__ Bhi, const __nv_bfloat16* __restrict__ Blo,
    long bOffZ,
    float* __restrict__ C, int ldc, long cOffZ,
    const float* __restrict__ bias, long biasOffZ)
{
    extern __shared__ char dsm[];
    const uint32_t base = smem_u32(dsm);

    const int tid = threadIdx.x, lane = tid & 31, w = tid >> 5;
    const int wm = w & 1, wn = w >> 1;            // 2 x 4 warp grid
    const int z = blockIdx.z;
    const long m0 = (long)blockIdx.y * 128;
    const long n0 = (long)blockIdx.x * 128;
    Ahi += z * aOffZ; Alo += z * aOffZ;
    Bhi += z * bOffZ; Blo += z * bOffZ;
    C += z * cOffZ;
    if (BIAS) bias += z * biasOffZ;

    float acc[4][4][4];
#pragma unroll
    for (int i = 0; i < 4; i++)
#pragma unroll
        for (int j = 0; j < 4; j++)
#pragma unroll
            for (int k = 0; k < 4; k++) acc[i][j][k] = 0.f;

    // ---- cp.async tile loader: one K-chunk of 32 into stage s ----
    auto loadChunk = [&](int s, int kc) {
        const long k0 = (long)kc * 32;
        const uint32_t ah = base + s * STAGE;
        const uint32_t al = ah + 8192;
        const uint32_t bh = ah + 16384;
        const uint32_t bl = ah + 24576;
#pragma unroll
        for (int i = 0; i < 2; i++) {
            const int idx = tid + 256 * i;
            const int r = idx >> 2, c = idx & 3;
            const uint32_t dst = swz(r, c);
            const long offA = (m0 + r) * lda + k0 + c * 8;
            CP16(ah + dst, Ahi + offA);
            CP16(al + dst, Alo + offA);
            const long offB = (n0 + r) * 1024 + k0 + c * 8;
            CP16(bh + dst, Bhi + offB);
            CP16(bl + dst, Blo + offB);
        }
        CP_COMMIT();
    };

    loadChunk(0, 0);

    for (int ch = 0; ch < 32; ch++) {
        const int s = ch & 1;
        if (ch < 31) {
            loadChunk(s ^ 1, ch + 1);
            asm volatile("cp.async.wait_group 1;" ::: "memory");
        } else {
            asm volatile("cp.async.wait_group 0;" ::: "memory");
        }
        __syncthreads();

        const uint32_t ah = base + s * STAGE;
        const uint32_t al = ah + 8192;
        const uint32_t bh = ah + 16384;
        const uint32_t bl = ah + 24576;

#pragma unroll
        for (int ks = 0; ks < 2; ks++) {
            uint32_t afh[4][4], afl[4][4], bfh[4][2], bfl[4][2];
            // A fragments: 4 m-frags of 16x16 (hi+lo)
            const int arow = wm * 64 + (lane & 15);
            const int akc = ks * 2 + (lane >> 4);
#pragma unroll
            for (int i = 0; i < 4; i++) {
                const uint32_t off = swz(arow + i * 16, akc);
                ldsm_x4(afh[i], ah + off);
                ldsm_x4(afl[i], al + off);
            }
            // B fragments: 4 n-frags of 16x8 (hi+lo); lanes 0-15 supply addrs
            const int brow = wn * 32 + (lane & 7);
            const int bkc = ks * 2 + ((lane >> 3) & 1);
#pragma unroll
            for (int j = 0; j < 4; j++) {
                const uint32_t off = swz(brow + j * 8, bkc);
                ldsm_x2(bfh[j], bh + off);
                ldsm_x2(bfl[j], bl + off);
            }
#pragma unroll
            for (int i = 0; i < 4; i++)
#pragma unroll
                for (int j = 0; j < 4; j++) {
                    mma_bf16(acc[i][j], afh[i], bfh[j]);
                    mma_bf16(acc[i][j], afh[i], bfl[j]);
                    mma_bf16(acc[i][j], afl[i], bfh[j]);
                }
        }
        __syncthreads();
    }

    // ---- epilogue: fragment layout -> global ----
    const int gr = lane >> 2, qd = lane & 3;
#pragma unroll
    for (int j = 0; j < 4; j++) {
        const long c = n0 + wn * 32 + j * 8 + qd * 2;
        float2 bv = make_float2(0.f, 0.f);
        if (BIAS) bv = *(const float2*)&bias[c];
#pragma unroll
        for (int i = 0; i < 4; i++) {
            const long r0 = m0 + wm * 64 + i * 16 + gr;
            float2 v0 = make_float2(acc[i][j][0] + bv.x, acc[i][j][1] + bv.y);
            float2 v1 = make_float2(acc[i][j][2] + bv.x, acc[i][j][3] + bv.y);
            if (RELU) {
                v0.x = fmaxf(v0.x, 0.f); v0.y = fmaxf(v0.y, 0.f);
                v1.x = fmaxf(v1.x, 0.f); v1.y = fmaxf(v1.y, 0.f);
            }
            *(float2*)&C[r0 * ldc + c] = v0;
            *(float2*)&C[(r0 + 8) * ldc + c] = v1;
        }
    }
}

// =============================================================================
// fp32 -> bf16 hi/lo split (vectorized by 4)
// =============================================================================
__global__ void split4(const float* __restrict__ src, __nv_bfloat16* __restrict__ hi,
                       __nv_bfloat16* __restrict__ lo, long n4)
{
    const long i = (long)blockIdx.x * 256 + threadIdx.x;
    if (i >= n4) return;
    float4 v = ((const float4*)src)[i];
    __nv_bfloat16 h0 = __float2bfloat16(v.x), h1 = __float2bfloat16(v.y);
    __nv_bfloat16 h2 = __float2bfloat16(v.z), h3 = __float2bfloat16(v.w);
    __nv_bfloat16 l0 = __float2bfloat16(v.x - __bfloat162float(h0));
    __nv_bfloat16 l1 = __float2bfloat16(v.y - __bfloat162float(h1));
    __nv_bfloat16 l2 = __float2bfloat16(v.z - __bfloat162float(h2));
    __nv_bfloat16 l3 = __float2bfloat16(v.w - __bfloat162float(h3));
    __nv_bfloat162 a, b;
    a.x = h0; a.y = h1; b.x = h2; b.y = h3;
    ((__nv_bfloat162*)hi)[2 * i] = a; ((__nv_bfloat162*)hi)[2 * i + 1] = b;
    a.x = l0; a.y = l1; b.x = l2; b.y = l3;
    ((__nv_bfloat162*)lo)[2 * i] = a; ((__nv_bfloat162*)lo)[2 * i + 1] = b;
}

// 1024x1024 transpose + split: dst[c][r] = src[r][c]
__global__ void tsplit(const float* __restrict__ src, __nv_bfloat16* __restrict__ hi,
                       __nv_bfloat16* __restrict__ lo)
{
    __shared__ float t[32][33];
    const int bx = blockIdx.x * 32, by = blockIdx.y * 32;
    const int tx = threadIdx.x;
    for (int j = threadIdx.y; j < 32; j += 8)
        t[j][tx] = src[(long)(by + j) * 1024 + bx + tx];
    __syncthreads();
    for (int j = threadIdx.y; j < 32; j += 8) {
        const float v = t[tx][j];
        const long o = (long)(bx + j) * 1024 + by + tx;
        __nv_bfloat16 h = __float2bfloat16(v);
        hi[o] = h;
        lo[o] = __float2bfloat16(v - __bfloat162float(h));
    }
}

// =============================================================================
// bias-derived vectors (fp32, tiny)
// =============================================================================
__global__ void vec_pre(const float* __restrict__ in_proj_w,
                        const float* __restrict__ in_proj_b,
                        const float* __restrict__ out_w,
                        const float* __restrict__ out_b)
{
    const int i = blockIdx.x * 256 + threadIdx.x;
    const float* wq = in_proj_w;
    const float* wk = in_proj_w + (long)D * D;
    const float* bq = in_proj_b;
    const float* bk = in_proj_b + D;
    const float* bv = in_proj_b + 2 * D;
    float vq = 0.f, vk = 0.f, bc = 0.f;
    for (int e = 0; e < D; e++) {
        vq = fmaf(bq[e], wk[(long)e * D + i], vq);
        vk = fmaf(bk[e], wq[(long)e * D + i], vk);
        bc = fmaf(out_w[(long)i * D + e], bv[e], bc);
    }
    g_vq[i] = vq; g_vk[i] = vk; g_bcomb[i] = bc + out_b[i];
    if (i == 0) {
        float c = 0.f;
        for (int e = 0; e < D; e++) c = fmaf(bq[e], bk[e], c);
        g_c0 = c;
    }
}

// =============================================================================
// d[b,s] = relu(h[s,b,:] . w2[s] + b2[s]) — one warp per row (fp32)
// =============================================================================
__global__ void cls_reduce(const float* __restrict__ cls_w2,
                           const float* __restrict__ cls_b2)
{
    const int warp = (blockIdx.x * blockDim.x + threadIdx.x) >> 5;
    const int lane = threadIdx.x & 31;
    const int s = warp >> 11;
    const int b = warp & 2047;
    const float* hrow = g_h + ((long)s * B + b) * H;
    const float* w = cls_w2 + (long)s * H;
    float acc = 0.f;
#pragma unroll
    for (int i = 0; i < H / 128; i++) {
        float4 hv = *(const float4*)&hrow[(lane + 32 * i) * 4];
        float4 wv = *(const float4*)&w[(lane + 32 * i) * 4];
        acc = fmaf(hv.x, wv.x, acc);
        acc = fmaf(hv.y, wv.y, acc);
        acc = fmaf(hv.z, wv.z, acc);
        acc = fmaf(hv.w, wv.w, acc);
    }
#pragma unroll
    for (int o = 16; o > 0; o >>= 1) acc += __shfl_xor_sync(~0u, acc, o);
    if (lane == 0) g_d[b * S + s] = fmaxf(acc + cls_b2[s], 0.f);
}

// =============================================================================
// Per-batch attention (fp32)
// =============================================================================
__global__ void __launch_bounds__(256) attn_kernel(
    const float* __restrict__ q, float* __restrict__ out)
{
    const int b = blockIdx.x;
    __shared__ float qs[32][132];
    __shared__ float qms[32][132];
    __shared__ float sc[32][33];
    __shared__ float vks[128];
    __shared__ float dd[32], rk[32], wa[32], wvv[32], da[16], dv[16];

    const int tid = threadIdx.x;
    const int s = tid >> 3;
    const int tb = tid & 7;
    const float* qb = q + (long)b * S * D;
    const float* qmb = g_qM + (long)b * S * D;

    if (tid < 32) dd[tid] = g_d[b * S + tid];

    float racc[4] = {0.f, 0.f, 0.f, 0.f};
    float rkacc = 0.f;

    for (int c = 0; c < D; c += 128) {
#pragma unroll
        for (int i = 0; i < 4; i++) {
            const int f = tid + 256 * i;
            const int r = f >> 5;
            const int c4 = (f & 31) << 2;
            *(float4*)&qs[r][c4] = *(const float4*)&qb[(long)r * D + c + c4];
            *(float4*)&qms[r][c4] = *(const float4*)&qmb[(long)r * D + c + c4];
        }
        if (tid < 32) *(float4*)&vks[tid * 4] = *(const float4*)&g_vk[c + tid * 4];
        __syncthreads();

#pragma unroll 4
        for (int k = 0; k < 128; k++) {
            const float av = qms[s][k];
#pragma unroll
            for (int j = 0; j < 4; j++)
                racc[j] = fmaf(av, qs[tb + 8 * j][k], racc[j]);
        }
        if (tid < 32) {
            float r2 = 0.f;
#pragma unroll 4
            for (int k = 0; k < 128; k++) r2 = fmaf(qs[tid][k], vks[k], r2);
            rkacc += r2;
        }
        __syncthreads();
    }

#pragma unroll
    for (int j = 0; j < 4; j++) sc[s][tb + 8 * j] = racc[j];
    if (tid < 32) rk[tid] = rkacc;
    __syncthreads();

    const int w = tid >> 5, lane = tid & 31;
    const float inv_sqrtD = 0.03125f;
    for (int rr = w * 4; rr < w * 4 + 4; rr++) {
        float v = (sc[rr][lane] + rk[rr] + g_c0) * inv_sqrtD;
        float mx = v;
#pragma unroll
        for (int o = 16; o > 0; o >>= 1) mx = fmaxf(mx, __shfl_xor_sync(~0u, mx, o));
        float e = __expf(v - mx);
        float sum = e;
#pragma unroll
        for (int o = 16; o > 0; o >>= 1) sum += __shfl_xor_sync(~0u, sum, o);
        sc[rr][lane] = e / sum;
    }
    __syncthreads();

    if (tid < 32) {
        const bool isA = tid < 16;
        const int i = tid & 15;
        float v = dd[tid];
        float mx = v;
#pragma unroll
        for (int o = 8; o > 0; o >>= 1) mx = fmaxf(mx, __shfl_xor_sync(~0u, mx, o));
        float e = __expf(v - mx);
        float sum = e;
#pragma unroll
        for (int o = 8; o > 0; o >>= 1) sum += __shfl_xor_sync(~0u, sum, o);
        const float p = e / sum;
        if (isA) da[i] = p; else dv[i] = p;
        const long bse = 3L * B * F;
        if (isA) out[bse + (long)b * P + i] = p;
        else     out[bse + (long)B * P + (long)b * P + i] = p;
    }
    __syncthreads();

    if (tid < 32) {
        float a = 0.f, v2 = 0.f;
#pragma unroll
        for (int ss = 0; ss < 16; ss++) a = fmaf(da[ss], sc[ss][tid], a);
#pragma unroll
        for (int ss = 0; ss < 16; ss++) v2 = fmaf(dv[ss], sc[16 + ss][tid], v2);
        wa[tid] = a;
        wvv[tid] = v2;
    }
    __syncthreads();

#pragma unroll
    for (int i = 0; i < 4; i++) {
        const int col = tid + 256 * i;
        float a = 0.f, v2 = 0.f;
#pragma unroll
        for (int t = 0; t < 32; t++) {
            const float x = qb[(long)t * D + col];
            a = fmaf(wa[t], x, a);
            v2 = fmaf(wvv[t], x, v2);
        }
        g_qv[(long)b * D + col] = a;
        g_qv[(long)B * D + (long)b * D + col] = v2;
    }
}

__global__ void fuse_avg()
{
    const long i = (long)blockIdx.x * 256 + threadIdx.x;
    g_fusion[i] = 0.5f * (g_av[i] + g_av[(long)B * D + i]);
}

__global__ void __launch_bounds__(128) ln_relu(
    const float* __restrict__ gm0, const float* __restrict__ be0,
    const float* __restrict__ gm1, const float* __restrict__ be1,
    const float* __restrict__ gm2, const float* __restrict__ be2,
    float* __restrict__ out)
{
    const int head = blockIdx.y, b = blockIdx.x, tid = threadIdx.x;
    const float* gm = head == 0 ? gm0 : (head == 1 ? gm1 : gm2);
    const float* be = head == 0 ? be0 : (head == 1 ? be1 : be2);
    const float* y = g_y + ((long)head * B + b) * F;

    float4 v = *(const float4*)&y[tid * 4];
    float s = v.x + v.y + v.z + v.w;
    float sq = v.x * v.x + v.y * v.y + v.z * v.z + v.w * v.w;
#pragma unroll
    for (int o = 16; o > 0; o >>= 1) {
        s += __shfl_xor_sync(~0u, s, o);
        sq += __shfl_xor_sync(~0u, sq, o);
    }
    __shared__ float ss[4], ssq[4];
    const int w = tid >> 5;
    if ((tid & 31) == 0) { ss[w] = s; ssq[w] = sq; }
    __syncthreads();
    s = ss[0] + ss[1] + ss[2] + ss[3];
    sq = ssq[0] + ssq[1] + ssq[2] + ssq[3];
    const float mean = s * (1.f / F);
    const float var = sq * (1.f / F) - mean * mean;
    const float rstd = rsqrtf(var + 1e-5f);

    float4 g4 = *(const float4*)&gm[tid * 4];
    float4 b4 = *(const float4*)&be[tid * 4];
    float4 o4;
    o4.x = fmaxf((v.x - mean) * rstd * g4.x + b4.x, 0.f);
    o4.y = fmaxf((v.y - mean) * rstd * g4.y + b4.y, 0.f);
    o4.z = fmaxf((v.z - mean) * rstd * g4.z + b4.z, 0.f);
    o4.w = fmaxf((v.w - mean) * rstd * g4.w + b4.w, 0.f);
    *(float4*)&out[((long)head * B + b) * F + tid * 4] = o4;
}

}  // namespace raff

// =============================================================================
// Launch
// =============================================================================
extern "C" void kernel_launch(void* const* d_in, const int* in_sizes, int n_in,
                              void* d_out, int out_size)
{
    using namespace raff;
    (void)in_sizes; (void)n_in; (void)out_size;

    const float* q         = (const float*)d_in[0];
    const float* in_proj_w = (const float*)d_in[1];
    const float* in_proj_b = (const float*)d_in[2];
    const float* out_w     = (const float*)d_in[3];
    const float* out_b     = (const float*)d_in[4];
    const float* cls_w1    = (const float*)d_in[5];
    const float* cls_b1    = (const float*)d_in[6];
    const float* cls_w2    = (const float*)d_in[7];
    const float* cls_b2    = (const float*)d_in[8];
    const float* fus_w     = (const float*)d_in[9];
    const float* fus_b     = (const float*)d_in[10];
    const float* fus_g     = (const float*)d_in[11];
    const float* fus_be    = (const float*)d_in[12];
    const float* pa_w      = (const float*)d_in[13];
    const float* pa_b      = (const float*)d_in[14];
    const float* pa_g      = (const float*)d_in[15];
    const float* pa_be     = (const float*)d_in[16];
    const float* pv_w      = (const float*)d_in[17];
    const float* pv_b      = (const float*)d_in[18];
    const float* pv_g      = (const float*)d_in[19];
    const float* pv_be     = (const float*)d_in[20];
    float* out = (float*)d_out;

    float *pMt, *pCov, *pqM, *ph, *pqv, *pav, *pfus, *py, *pvq, *pbcomb;
    __nv_bfloat16 *qhi, *qlo, *w1hi, *w1lo, *WqThi, *WqTlo, *WkThi, *WkTlo,
        *WvThi, *WvTlo, *owhi, *owlo, *mthi, *mtlo, *covhi, *covlo,
        *qvhi, *qvlo, *xhi, *xlo, *hwhi, *hwlo;
    cudaGetSymbolAddress((void**)&pMt, g_Mt);
    cudaGetSymbolAddress((void**)&pCov, g_Cov);
    cudaGetSymbolAddress((void**)&pqM, g_qM);
    cudaGetSymbolAddress((void**)&ph, g_h);
    cudaGetSymbolAddress((void**)&pqv, g_qv);
    cudaGetSymbolAddress((void**)&pav, g_av);
    cudaGetSymbolAddress((void**)&pfus, g_fusion);
    cudaGetSymbolAddress((void**)&py, g_y);
    cudaGetSymbolAddress((void**)&pvq, g_vq);
    cudaGetSymbolAddress((void**)&pbcomb, g_bcomb);
    cudaGetSymbolAddress((void**)&qhi, g_q_hi);
    cudaGetSymbolAddress((void**)&qlo, g_q_lo);
    cudaGetSymbolAddress((void**)&w1hi, g_w1_hi);
    cudaGetSymbolAddress((void**)&w1lo, g_w1_lo);
    cudaGetSymbolAddress((void**)&WqThi, g_WqT_hi);
    cudaGetSymbolAddress((void**)&WqTlo, g_WqT_lo);
    cudaGetSymbolAddress((void**)&WkThi, g_WkT_hi);
    cudaGetSymbolAddress((void**)&WkTlo, g_WkT_lo);
    cudaGetSymbolAddress((void**)&WvThi, g_WvT_hi);
    cudaGetSymbolAddress((void**)&WvTlo, g_WvT_lo);
    cudaGetSymbolAddress((void**)&owhi, g_ow_hi);
    cudaGetSymbolAddress((void**)&owlo, g_ow_lo);
    cudaGetSymbolAddress((void**)&mthi, g_mt_hi);
    cudaGetSymbolAddress((void**)&mtlo, g_mt_lo);
    cudaGetSymbolAddress((void**)&covhi, g_cov_hi);
    cudaGetSymbolAddress((void**)&covlo, g_cov_lo);
    cudaGetSymbolAddress((void**)&qvhi, g_qv_hi);
    cudaGetSymbolAddress((void**)&qvlo, g_qv_lo);
    cudaGetSymbolAddress((void**)&xhi, g_x_hi);
    cudaGetSymbolAddress((void**)&xlo, g_x_lo);
    cudaGetSymbolAddress((void**)&hwhi, g_hw_hi);
    cudaGetSymbolAddress((void**)&hwlo, g_hw_lo);

    cudaFuncSetAttribute((const void*)bsgemm<false, false>,
                         cudaFuncAttributeMaxDynamicSharedMemorySize, GEMM_SMEM);
    cudaFuncSetAttribute((const void*)bsgemm<false, true>,
                         cudaFuncAttributeMaxDynamicSharedMemorySize, GEMM_SMEM);
    cudaFuncSetAttribute((const void*)bsgemm<true, true>,
                         cudaFuncAttributeMaxDynamicSharedMemorySize, GEMM_SMEM);

    // 1) bias-derived vectors
    vec_pre<<<D / 256, 256>>>(in_proj_w, in_proj_b, out_w, out_b);

    // 2) conversions of inputs
    split4<<<(int)(NQ / 4 / 256), 256>>>(q, qhi, qlo, NQ / 4);
    split4<<<(int)((long)S * H * D / 4 / 256), 256>>>(cls_w1, w1hi, w1lo, (long)S * H * D / 4);
    split4<<<D * D / 4 / 256, 256>>>(out_w, owhi, owlo, D * D / 4);
    split4<<<F * D / 4 / 256, 256>>>(fus_w, hwhi, hwlo, (long)F * D / 4);
    split4<<<F * D / 4 / 256, 256>>>(pa_w, hwhi + (long)F * D, hwlo + (long)F * D, (long)F * D / 4);
    split4<<<F * D / 4 / 256, 256>>>(pv_w, hwhi + 2L * F * D, hwlo + 2L * F * D, (long)F * D / 4);
    tsplit<<<dim3(32, 32), dim3(32, 8)>>>(in_proj_w, WqThi, WqTlo);
    tsplit<<<dim3(32, 32), dim3(32, 8)>>>(in_proj_w + (long)D * D, WkThi, WkTlo);
    tsplit<<<dim3(32, 32), dim3(32, 8)>>>(in_proj_w + 2L * D * D, WvThi, WvTlo);

    // 3) Mt = WkT * WqT^T, then split
    bsgemm<false, false><<<dim3(8, 8), 256, GEMM_SMEM>>>(
        WkThi, WkTlo, D, 0L, WqThi, WqTlo, 0L, pMt, D, 0L, nullptr, 0L);
    split4<<<D * D / 4 / 256, 256>>>(pMt, mthi, mtlo, D * D / 4);

    // 4) Cov = out_w * WvT^T, then split
    bsgemm<false, false><<<dim3(8, 8), 256, GEMM_SMEM>>>(
        owhi, owlo, D, 0L, WvThi, WvTlo, 0L, pCov, D, 0L, nullptr, 0L);
    split4<<<D * D / 4 / 256, 256>>>(pCov, covhi, covlo, D * D / 4);

    // 5) qM = q * Mt^T + vq   [65536 x 1024 x 1024]
    bsgemm<false, true><<<dim3(8, 512), 256, GEMM_SMEM>>>(
        qhi, qlo, (long)D, 0L, mthi, mtlo, 0L, pqM, D, 0L, pvq, 0L);

    // 6) h[s] = relu(q_s * w1[s]^T + b1[s])  batched z = s
    bsgemm<true, true><<<dim3(4, 16, 32), 256, GEMM_SMEM>>>(
        qhi, qlo, (long)S * D, (long)D, w1hi, w1lo, (long)H * D,
        ph, H, (long)B * H, cls_b1, (long)H);

    // 7) d logits (fp32)
    cls_reduce<<<(B * S) / 8, 256>>>(cls_w2, cls_b2);

    // 8) attention + softmaxes + weighted q sums (fp32)
    attn_kernel<<<B, 256>>>(q, out);

    // 9) split qv, [audio; video] = qv * Cov^T + bcomb
    split4<<<(int)(2L * B * D / 4 / 256), 256>>>(pqv, qvhi, qvlo, 2L * B * D / 4);
    bsgemm<false, true><<<dim3(8, 32), 256, GEMM_SMEM>>>(
        qvhi, qvlo, (long)D, 0L, covhi, covlo, 0L, pav, D, 0L, pbcomb, 0L);

    // 10) fusion, split head inputs
    fuse_avg<<<(B * D) / 256, 256>>>();
    split4<<<(int)((long)B * D / 4 / 256), 256>>>(pfus, xhi, xlo, (long)B * D / 4);
    split4<<<(int)(2L * B * D / 4 / 256), 256>>>(pav, xhi + (long)B * D, xlo + (long)B * D,
                                                 2L * B * D / 4);

    // 11) three head GEMMs: y = x * W^T + b  [2048 x 512 x 1024]
    bsgemm<false, true><<<dim3(4, 16), 256, GEMM_SMEM>>>(
        xhi, xlo, (long)D, 0L, hwhi, hwlo, 0L, py, F, 0L, fus_b, 0L);
    bsgemm<false, true><<<dim3(4, 16), 256, GEMM_SMEM>>>(
        xhi + (long)B * D, xlo + (long)B * D, (long)D, 0L,
        hwhi + (long)F * D, hwlo + (long)F * D, 0L, py + (long)B * F, F, 0L, pa_b, 0L);
    bsgemm<false, true><<<dim3(4, 16), 256, GEMM_SMEM>>>(
        xhi + 2L * B * D, xlo + 2L * B * D, (long)D, 0L,
        hwhi + 2L * F * D, hwlo + 2L * F * D, 0L, py + 2L * B * F, F, 0L, pv_b, 0L);

    // 12) LayerNorm + ReLU -> final outputs
    ln_relu<<<dim3(B, 3), 128>>>(fus_g, fus_be, pa_g, pa_be, pv_g, pv_be, out);
}